// round 7
// baseline (speedup 1.0000x reference)
#include <cuda_runtime.h>
#include <cstdint>

#define MM_    3844
#define CIN_   128
#define COUT_  256
#define KTOT_  1152
#define BM_    256
#define BN_    128
#define NTHR_  256
#define NT_    72

// smem word offsets (stride 16 words/row, swizzled — no padding)
#define OFF_A0  0
#define OFF_A1  4096
#define OFF_B0  8192
#define OFF_B1  10240
#define OFF_BBS 12288
#define SMEM_BYTES ((OFF_BBS + BN_) * 4)   // 49664

__device__ __forceinline__ uint32_t to_tf32(float x) {
    uint32_t r;
    asm("cvt.rna.tf32.f32 %0, %1;" : "=r"(r) : "f"(x));
    return r;
}

__device__ __forceinline__ void mma_tf32(float c[4],
                                         uint32_t a0, uint32_t a1, uint32_t a2, uint32_t a3,
                                         uint32_t b0, uint32_t b1) {
    asm volatile(
        "mma.sync.aligned.m16n8k8.row.col.f32.tf32.tf32.f32 "
        "{%0,%1,%2,%3}, {%4,%5,%6,%7}, {%8,%9}, {%0,%1,%2,%3};"
        : "+f"(c[0]), "+f"(c[1]), "+f"(c[2]), "+f"(c[3])
        : "r"(a0), "r"(a1), "r"(a2), "r"(a3), "r"(b0), "r"(b1));
}

__global__ void __launch_bounds__(NTHR_, 1)
conv_mma_kernel(const float* __restrict__ X, const float* __restrict__ W,
                const float* __restrict__ bias, const float* __restrict__ Werr,
                const float* __restrict__ Berr, float* __restrict__ out)
{
    extern __shared__ float smf[];
    uint32_t* const Asm[2] = {(uint32_t*)(smf + OFF_A0), (uint32_t*)(smf + OFF_A1)};
    uint32_t* const Bsm[2] = {(uint32_t*)(smf + OFF_B0), (uint32_t*)(smf + OFF_B1)};
    float* const bbs = smf + OFF_BBS;

    const int tid  = threadIdx.x;
    const int lane = tid & 31;
    const int wid  = tid >> 5;        // 0..7
    const int wm   = wid >> 1;        // 0..3 (M dir, 64 rows)
    const int wn   = wid & 1;         // 0..1 (N dir, 64 cols)
    const int g    = lane >> 2;       // 0..7
    const int tq   = lane & 3;        // 0..3

    const int b  = blockIdx.z;
    const int m0 = blockIdx.y * BM_;
    const int n0 = blockIdx.x * BN_;

    if (tid < BN_) bbs[tid] = bias[n0 + tid] * Berr[b * COUT_ + n0 + tid];

    // ---- A fill: thread = one m-row, 16 k floats (4 LDG.128 -> 4 STS.128)
    const int arow = tid;
    const int agm  = m0 + arow;
    const bool a_ok = (agm < MM_);
    const int amc = a_ok ? agm : 0;
    const int aho = amc / 62, awo = amc - aho * 62;
    const float* Xp = X + (((size_t)b * 64 + aho) * 64 + awo) * CIN_;
    const uint32_t aswz = ((uint32_t)arow >> 1) & 3;

    // ---- B fill: warp (wid>>2) -> k-half base, (wid&3) -> 32-n block; 2 its (k, k+8)
    const int kq  = lane & 3;
    const int nq  = lane >> 2;
    const int kb0 = (wid >> 2) * 4 + kq;            // 0..7
    const int nld = (wid & 3) * 32 + nq * 4;        // LDG n col
    const int nrw = (wid & 3) * 32 + lane;          // post-transpose n row
    const uint32_t nrswz = ((uint32_t)nrw >> 1) & 3;
    const int bchunk0 = (wid >> 2);                 // chunk for it=0 (it=1: +2)
    const float* Wp = W + n0 + nld;
    const float* Ep = Werr + (size_t)b * ((size_t)KTOT_ * COUT_) + n0 + nld;

    float acc[4][8][4];
    #pragma unroll
    for (int i = 0; i < 4; i++)
        #pragma unroll
        for (int j = 0; j < 8; j++)
            #pragma unroll
            for (int q = 0; q < 4; q++) acc[i][j][q] = 0.0f;

    float4 ax[4];          // A staging: 16 floats
    float4 rw[2], re[2];   // B staging

    auto load_regs = [&](int u) {
        const int khw = u >> 3, cc = u & 7;
        const int kh = khw / 3, kw = khw - 3 * kh;
        const int aoff = (kh * 64 + kw) * CIN_ + cc * 16;
        #pragma unroll
        for (int j = 0; j < 4; j++)
            ax[j] = a_ok ? *(const float4*)(Xp + aoff + 4 * j)
                         : make_float4(0.f, 0.f, 0.f, 0.f);
        const int kk = khw * CIN_ + cc * 16;
        #pragma unroll
        for (int it = 0; it < 2; it++) {
            size_t gi = (size_t)(kk + kb0 + 8 * it) * COUT_;
            rw[it] = *(const float4*)(Wp + gi);
            re[it] = *(const float4*)(Ep + gi);
        }
    };

    auto sts_regs = [&](int s) {
        // A: natural k order, chunk-swizzled STS.128
        uint32_t* An = Asm[s] + arow * 16;
        #pragma unroll
        for (int j = 0; j < 4; j++) {
            uint4 v = {to_tf32(ax[j].x), to_tf32(ax[j].y),
                       to_tf32(ax[j].z), to_tf32(ax[j].w)};
            *(uint4*)(An + 4 * ((uint32_t)j ^ aswz)) = v;
        }
        // B: fuse W*Werr, cvt, 4x4 butterfly transpose, swizzled STS.128
        #pragma unroll
        for (int it = 0; it < 2; it++) {
            uint32_t v0 = to_tf32(rw[it].x * re[it].x);
            uint32_t v1 = to_tf32(rw[it].y * re[it].y);
            uint32_t v2 = to_tf32(rw[it].z * re[it].z);
            uint32_t v3 = to_tf32(rw[it].w * re[it].w);
            // stage 1 (xor 1)
            uint32_t w0 = __shfl_xor_sync(0xffffffffu, v1, 1);
            uint32_t w1 = __shfl_xor_sync(0xffffffffu, v0, 1);
            uint32_t w2 = __shfl_xor_sync(0xffffffffu, v3, 1);
            uint32_t w3 = __shfl_xor_sync(0xffffffffu, v2, 1);
            if (kq & 1) { v0 = w0; v2 = w2; } else { v1 = w1; v3 = w3; }
            // stage 2 (xor 2)
            uint32_t u0 = __shfl_xor_sync(0xffffffffu, v2, 2);
            uint32_t u1 = __shfl_xor_sync(0xffffffffu, v3, 2);
            uint32_t u2 = __shfl_xor_sync(0xffffffffu, v0, 2);
            uint32_t u3 = __shfl_xor_sync(0xffffffffu, v1, 2);
            if (kq & 2) { v0 = u0; v1 = u1; } else { v2 = u2; v3 = u3; }
            // lane holds n-row nrw, k = chunk natural order
            uint32_t ch = (uint32_t)(bchunk0 + 2 * it) ^ nrswz;
            *(uint4*)(Bsm[s] + nrw * 16 + 4 * ch) = make_uint4(v0, v1, v2, v3);
        }
    };

    load_regs(0);
    sts_regs(0);
    __syncthreads();

    for (int t = 0; t < NT_; t++) {
        const int cur = t & 1;
        const bool hn = (t + 1 < NT_);
        if (hn) load_regs(t + 1);

        const uint32_t* Ab = Asm[cur];
        const uint32_t* Bb = Bsm[cur];

        // B fragments: one LDS.128 per nt covers both HMMA k-groups
        uint4 bw[8];
        #pragma unroll
        for (int nt = 0; nt < 8; nt++) {
            int nb2 = wn * 64 + nt * 8 + g;
            bw[nt] = *(const uint4*)(Bb + nb2 * 16 +
                                     4 * ((uint32_t)tq ^ (((uint32_t)nb2 >> 1) & 3)));
        }
        #pragma unroll
        for (int mt = 0; mt < 4; mt++) {
            int ra = wm * 64 + mt * 16 + g;
            uint4 a0v = *(const uint4*)(Ab + ra * 16 +
                                        4 * ((uint32_t)tq ^ (((uint32_t)ra >> 1) & 3)));
            uint4 a8v = *(const uint4*)(Ab + (ra + 8) * 16 +
                                        4 * ((uint32_t)tq ^ (((uint32_t)(ra + 8) >> 1) & 3)));
            #pragma unroll
            for (int nt = 0; nt < 8; nt++)
                mma_tf32(acc[mt][nt], a0v.x, a8v.x, a0v.y, a8v.y, bw[nt].x, bw[nt].y);
            #pragma unroll
            for (int nt = 0; nt < 8; nt++)
                mma_tf32(acc[mt][nt], a0v.z, a8v.z, a0v.w, a8v.w, bw[nt].z, bw[nt].w);
        }

        if (hn) sts_regs((t + 1) & 1);
        __syncthreads();
    }

    // ---- Epilogue: acc + bias*Berr -> out
    #pragma unroll
    for (int mt = 0; mt < 4; mt++) {
        #pragma unroll
        for (int h = 0; h < 2; h++) {
            int rg = m0 + wm * 64 + mt * 16 + g + h * 8;
            if (rg < MM_) {
                float* op = out + ((size_t)b * MM_ + rg) * COUT_ + n0 + wn * 64 + tq * 2;
                #pragma unroll
                for (int nt = 0; nt < 8; nt++) {
                    float2 bb = *(const float2*)&bbs[wn * 64 + nt * 8 + tq * 2];
                    float2 v;
                    v.x = acc[mt][nt][2 * h + 0] + bb.x;
                    v.y = acc[mt][nt][2 * h + 1] + bb.y;
                    *(float2*)(op + nt * 8) = v;
                }
            }
        }
    }
}

extern "C" void kernel_launch(void* const* d_in, const int* in_sizes, int n_in,
                              void* d_out, int out_size)
{
    const float* X    = (const float*)d_in[0];
    const float* W    = (const float*)d_in[1];
    const float* bias = (const float*)d_in[2];
    const float* Werr = (const float*)d_in[3];
    const float* Berr = (const float*)d_in[4];
    float* out = (float*)d_out;

    cudaFuncSetAttribute(conv_mma_kernel,
                         cudaFuncAttributeMaxDynamicSharedMemorySize, SMEM_BYTES);
    dim3 grid(COUT_ / BN_, (MM_ + BM_ - 1) / BM_, 64);   // (2, 16, 64)
    conv_mma_kernel<<<grid, NTHR_, SMEM_BYTES>>>(X, W, bias, Werr, Berr, out);
}

// round 8
// speedup vs baseline: 1.2722x; 1.2722x over previous
#include <cuda_runtime.h>
#include <cstdint>

#define MM_    3844
#define CIN_   128
#define COUT_  256
#define KTOT_  1152
#define BM_    256
#define BN_    128
#define NTHR_  256
#define NT_    72

#define WPS    8192                 // words per stage (A 4096 | W 2048 | E 2048)
#define OFFA(s) ((s) * WPS)
#define OFFW(s) ((s) * WPS + 4096)
#define OFFE(s) ((s) * WPS + 6144)
#define OFF_BBS (3 * WPS)
#define SMEM_BYTES ((OFF_BBS + BN_) * 4)   // 98816

__device__ __forceinline__ uint32_t to_tf32(float x) {
    uint32_t r;
    asm("cvt.rna.tf32.f32 %0, %1;" : "=r"(r) : "f"(x));
    return r;
}
__device__ __forceinline__ uint32_t smem_u32(const void* p) {
    uint32_t a;
    asm("{ .reg .u64 t; cvta.to.shared.u64 t, %1; cvt.u32.u64 %0, t; }" : "=r"(a) : "l"(p));
    return a;
}
__device__ __forceinline__ void cp16(uint32_t dst, const float* src, int src_bytes) {
    asm volatile("cp.async.cg.shared.global [%0], [%1], 16, %2;"
                 :: "r"(dst), "l"(src), "r"(src_bytes) : "memory");
}
#define CP_COMMIT() asm volatile("cp.async.commit_group;" ::: "memory")
#define CP_WAIT1()  asm volatile("cp.async.wait_group 1;" ::: "memory")

__device__ __forceinline__ void mma_tf32(float c[4],
                                         uint32_t a0, uint32_t a1, uint32_t a2, uint32_t a3,
                                         uint32_t b0, uint32_t b1) {
    asm volatile(
        "mma.sync.aligned.m16n8k8.row.col.f32.tf32.tf32.f32 "
        "{%0,%1,%2,%3}, {%4,%5,%6,%7}, {%8,%9}, {%0,%1,%2,%3};"
        : "+f"(c[0]), "+f"(c[1]), "+f"(c[2]), "+f"(c[3])
        : "r"(a0), "r"(a1), "r"(a2), "r"(a3), "r"(b0), "r"(b1));
}

__global__ void __launch_bounds__(NTHR_, 1)
conv_mma_kernel(const float* __restrict__ X, const float* __restrict__ W,
                const float* __restrict__ bias, const float* __restrict__ Werr,
                const float* __restrict__ Berr, float* __restrict__ out)
{
    extern __shared__ float smf[];
    const uint32_t sb = smem_u32(smf);
    float* const bbs = smf + OFF_BBS;

    const int tid  = threadIdx.x;
    const int lane = tid & 31;
    const int wid  = tid >> 5;        // 0..7
    const int wm   = wid >> 1;        // 0..3 (M dir, 64 rows)
    const int wn   = wid & 1;         // 0..1 (N dir, 64 cols)
    const int g    = lane >> 2;       // 0..7
    const int tq   = lane & 3;        // 0..3

    const int b  = blockIdx.z;
    const int m0 = blockIdx.y * BM_;
    const int n0 = blockIdx.x * BN_;

    if (tid < BN_) bbs[tid] = bias[n0 + tid] * Berr[b * COUT_ + n0 + tid];

    // ---- A prefetch mapping: thread = one m-row (tid), 4 chunks of 16B
    const int agm  = m0 + tid;
    const bool a_ok = (agm < MM_);
    const int amc = a_ok ? agm : 0;
    const int aho = amc / 62, awo = amc - aho * 62;
    const float* Xp = X + (((size_t)b * 64 + aho) * 64 + awo) * CIN_;
    const int a_sz = a_ok ? 16 : 0;
    const uint32_t aswz = ((uint32_t)tid >> 1) & 3;
    const uint32_t a_dst_row = sb + (uint32_t)tid * 64;     // 16 words = 64B per row

    // ---- W/E prefetch mapping: thread covers (k = tid>>5 and +8, nchunk = tid&31)
    const int pk  = tid >> 5;                // 0..7
    const int pnc = tid & 31;                // 0..31
    const uint32_t psw = (uint32_t)(pk & 3) << 1;            // same for pk and pk+8
    const float* Wp = W + n0 + 4 * pnc;
    const float* Ep = Werr + (size_t)b * ((size_t)KTOT_ * COUT_) + n0 + 4 * pnc;

    float acc[4][8][4];
    #pragma unroll
    for (int i = 0; i < 4; i++)
        #pragma unroll
        for (int j = 0; j < 8; j++)
            #pragma unroll
            for (int q = 0; q < 4; q++) acc[i][j][q] = 0.0f;

    auto prefetch = [&](int u, int s) {
        const int khw = u >> 3, cc = u & 7;
        const int kh = khw / 3, kw = khw - 3 * kh;
        // A: 4 chunks of row tid
        const float* asrc = Xp + (kh * 64 + kw) * CIN_ + cc * 16;
        const uint32_t ad = a_dst_row + (uint32_t)OFFA(s) * 4;
        #pragma unroll
        for (int c = 0; c < 4; c++)
            cp16(ad + 16 * ((uint32_t)c ^ aswz), asrc + 4 * c, a_sz);
        // W, E: rows pk and pk+8
        const int kk = khw * CIN_ + cc * 16;
        #pragma unroll
        for (int h = 0; h < 2; h++) {
            const int k = pk + 8 * h;
            const size_t gofs = (size_t)(kk + k) * COUT_;
            const uint32_t drow = (uint32_t)k * 512 + 16 * ((uint32_t)pnc ^ psw);
            cp16(sb + (uint32_t)OFFW(s) * 4 + drow, Wp + gofs, 16);
            cp16(sb + (uint32_t)OFFE(s) * 4 + drow, Ep + gofs, 16);
        }
    };

    prefetch(0, 0); CP_COMMIT();
    prefetch(1, 1); CP_COMMIT();

    // frag address precompute (word indices)
    // A: row r -> r*16 + 4*(chunk ^ ((r>>1)&3)) + tq
    // B: k -> k*128 + 4*((c>>2) ^ ((k&3)<<1)) + (c&3), with (k&3)==tq for both k-groups
    const uint32_t bsw = (uint32_t)tq << 1;

    for (int t = 0; t < NT_; t++) {
        CP_WAIT1();
        __syncthreads();
        const int s = t % 3;
        if (t + 2 < NT_) prefetch(t + 2, (t + 2) % 3);
        CP_COMMIT();

        const float* Ab = smf + OFFA(s);
        const float* Wb = smf + OFFW(s);
        const float* Eb = smf + OFFE(s);

        #pragma unroll
        for (int k8 = 0; k8 < 2; k8++) {
            const uint32_t ch0 = (uint32_t)(k8 * 2);
            // ---- A fragments (raw -> cvt.rna)
            uint32_t af[4][4];
            #pragma unroll
            for (int mt = 0; mt < 4; mt++) {
                const int r  = wm * 64 + mt * 16 + g;
                const uint32_t sw = ((uint32_t)r >> 1) & 3;
                const float* a0p = Ab + r * 16 + tq;
                const float* a1p = Ab + (r + 8) * 16 + tq;
                af[mt][0] = to_tf32(a0p[4 * (ch0 ^ sw)]);
                af[mt][1] = to_tf32(a1p[4 * (ch0 ^ sw)]);
                af[mt][2] = to_tf32(a0p[4 * ((ch0 + 1) ^ sw)]);
                af[mt][3] = to_tf32(a1p[4 * ((ch0 + 1) ^ sw)]);
            }
            // ---- B fragments (W*Werr -> cvt.rna)
            uint32_t bf[8][2];
            #pragma unroll
            for (int nt = 0; nt < 8; nt++) {
                const int c = wn * 64 + nt * 8 + g;
                const uint32_t cw = 4 * (((uint32_t)c >> 2) ^ bsw) + ((uint32_t)c & 3);
                const int k1 = k8 * 8 + tq;
                const int k2 = k1 + 4;
                bf[nt][0] = to_tf32(Wb[k1 * 128 + cw] * Eb[k1 * 128 + cw]);
                bf[nt][1] = to_tf32(Wb[k2 * 128 + cw] * Eb[k2 * 128 + cw]);
            }
            #pragma unroll
            for (int mt = 0; mt < 4; mt++)
                #pragma unroll
                for (int nt = 0; nt < 8; nt++)
                    mma_tf32(acc[mt][nt], af[mt][0], af[mt][1], af[mt][2], af[mt][3],
                             bf[nt][0], bf[nt][1]);
        }
    }

    // ---- Epilogue: acc + bias*Berr -> out
    #pragma unroll
    for (int mt = 0; mt < 4; mt++) {
        #pragma unroll
        for (int h = 0; h < 2; h++) {
            int rg = m0 + wm * 64 + mt * 16 + g + h * 8;
            if (rg < MM_) {
                float* op = out + ((size_t)b * MM_ + rg) * COUT_ + n0 + wn * 64 + tq * 2;
                #pragma unroll
                for (int nt = 0; nt < 8; nt++) {
                    float2 bb = *(const float2*)&bbs[wn * 64 + nt * 8 + tq * 2];
                    float2 v;
                    v.x = acc[mt][nt][2 * h + 0] + bb.x;
                    v.y = acc[mt][nt][2 * h + 1] + bb.y;
                    *(float2*)(op + nt * 8) = v;
                }
            }
        }
    }
}

extern "C" void kernel_launch(void* const* d_in, const int* in_sizes, int n_in,
                              void* d_out, int out_size)
{
    const float* X    = (const float*)d_in[0];
    const float* W    = (const float*)d_in[1];
    const float* bias = (const float*)d_in[2];
    const float* Werr = (const float*)d_in[3];
    const float* Berr = (const float*)d_in[4];
    float* out = (float*)d_out;

    cudaFuncSetAttribute(conv_mma_kernel,
                         cudaFuncAttributeMaxDynamicSharedMemorySize, SMEM_BYTES);
    dim3 grid(COUT_ / BN_, (MM_ + BM_ - 1) / BM_, 64);   // (2, 16, 64)
    conv_mma_kernel<<<grid, NTHR_, SMEM_BYTES>>>(X, W, bias, Werr, Berr, out);
}